// round 5
// baseline (speedup 1.0000x reference)
#include <cuda_runtime.h>
#include <cstdint>

// PowerSpectrum: values[S,N,L,M,Q] f32 -> out[S,N,L*Q*Q] f32
// out[s,n,l,q,p] = rsqrt(2l+1) * sum_{m<2l+1} v[m,q]*v[m,p]
// Shapes: S=4, N=2000, L=4, M=7, Q=64.
//
// R4 (88.5us) was DRAM-write-bound at 76.4% with one CTA per (s,n,l).
// R5: one CTA per (s,n) group -> 8000 CTAs, each loads 7KB input once,
// computes all 4 l-tiles (compile-time m-counts 1/3/5/7), streams 64KB
// of contiguous output. Uniform CTA work, longer store streams, fewer
// per-CTA fixed costs.

#define L_DIM 4
#define M_DIM 7
#define Q_DIM 64
#define TILE_IN   (M_DIM * Q_DIM)          // 448 floats per (s,n,l)
#define TILE_OUT  (Q_DIM * Q_DIM)          // 4096 floats per (s,n,l)
#define GROUP_IN  (L_DIM * TILE_IN)        // 1792 floats per (s,n)
#define GROUP_OUT (L_DIM * TILE_OUT)       // 16384 floats per (s,n)

template<int MM>
__device__ __forceinline__ void gram_tile(const float (*__restrict__ sv)[Q_DIM],
                                          float* __restrict__ ot, int tid)
{
    const int p0 = (tid & 15) << 2;  // 0,4,...,60
    const int q0 = (tid >> 4) << 3;  // 0,8,...,56

    const float cg = rsqrtf((float)MM);

    float4 acc[8];
    #pragma unroll
    for (int r = 0; r < 8; r++) acc[r] = make_float4(0.f, 0.f, 0.f, 0.f);

    #pragma unroll
    for (int m = 0; m < MM; m++) {
        const float4 b  = *(const float4*)&sv[m][p0];
        const float4 a0 = *(const float4*)&sv[m][q0];
        const float4 a1 = *(const float4*)&sv[m][q0 + 4];
        const float ar[8] = {a0.x, a0.y, a0.z, a0.w, a1.x, a1.y, a1.z, a1.w};
        #pragma unroll
        for (int r = 0; r < 8; r++) {
            acc[r].x += ar[r] * b.x;
            acc[r].y += ar[r] * b.y;
            acc[r].z += ar[r] * b.z;
            acc[r].w += ar[r] * b.w;
        }
    }

    // Streaming stores; 16 threads (same qt) cover one 256B row, warps
    // cover contiguous 4KB row blocks.
    #pragma unroll
    for (int r = 0; r < 8; r++) {
        float4 o = make_float4(acc[r].x * cg, acc[r].y * cg,
                               acc[r].z * cg, acc[r].w * cg);
        __stcs((float4*)(ot + (size_t)(q0 + r) * Q_DIM + p0), o);
    }
}

__global__ __launch_bounds__(128)
void powerspectrum_kernel(const float* __restrict__ values,
                          float* __restrict__ out)
{
    const int grp = blockIdx.x;            // (s*N + n)
    const float* vt = values + (size_t)grp * GROUP_IN;
    float*       ot = out    + (size_t)grp * GROUP_OUT;

    __shared__ float sv[L_DIM][M_DIM][Q_DIM];   // 7168 B

    const int tid = threadIdx.x;

    // Front-batched coalesced load: 448 float4, 3-4 per thread (high MLP).
    const float4* src = (const float4*)vt;
    float4*       dst = (float4*)&sv[0][0][0];
    #pragma unroll
    for (int i = tid; i < GROUP_IN / 4; i += 128)
        dst[i] = src[i];
    __syncthreads();

    gram_tile<1>(sv[0], ot + 0 * TILE_OUT, tid);
    gram_tile<3>(sv[1], ot + 1 * TILE_OUT, tid);
    gram_tile<5>(sv[2], ot + 2 * TILE_OUT, tid);
    gram_tile<7>(sv[3], ot + 3 * TILE_OUT, tid);
}

extern "C" void kernel_launch(void* const* d_in, const int* in_sizes, int n_in,
                              void* d_out, int out_size)
{
    const float* values = (const float*)d_in[0];
    float* out = (float*)d_out;

    const int groups = in_sizes[0] / GROUP_IN;   // S*N = 8000

    powerspectrum_kernel<<<groups, 128>>>(values, out);
}